// round 2
// baseline (speedup 1.0000x reference)
#include <cuda_runtime.h>
#include <cuda_bf16.h>

#define NN 50000
#define EE 800000
#define HH 64
#define GG 16
#define BN_EPS 1e-5f
#define ROWS 8

// -------- scratch (no allocations allowed) --------
__device__ float d_agg[NN * HH];
__device__ float d_h[NN * HH];      // pre-BN MLP output
__device__ float d_x1[NN * HH];     // layer-1 output
__device__ float d_sum[HH];
__device__ float d_sumsq[HH];
__device__ float d_gsum[GG * HH];
__device__ float d_gcnt[GG];

// -------- edge scatter: agg[dst] += x[src], vectorized red.global.add.v4.f32 --------
__global__ __launch_bounds__(256) void scatter_kernel(
    const float* __restrict__ x, const int* __restrict__ ei,
    float* __restrict__ agg)
{
    long long idx = (long long)blockIdx.x * blockDim.x + threadIdx.x;
    if (idx >= (long long)EE * 16) return;
    int e = (int)(idx >> 4);
    int q = (int)(idx & 15);
    int s = ei[e];
    int d = ei[EE + e];
    const float4 v = *reinterpret_cast<const float4*>(x + (long long)s * HH + q * 4);
    float* p = agg + (long long)d * HH + q * 4;
    asm volatile("red.global.add.v4.f32 [%0], {%1,%2,%3,%4};"
                 :: "l"(p), "f"(v.x), "f"(v.y), "f"(v.z), "f"(v.w) : "memory");
}

// -------- fused: h=(x+agg); h1=relu(h@W1+b1); h2=h1@W2+b2; store h2; BN stats --------
__global__ __launch_bounds__(512) void mlp_kernel(
    const float* __restrict__ x, const float* __restrict__ agg,
    const float* __restrict__ W1, const float* __restrict__ b1,
    const float* __restrict__ W2, const float* __restrict__ b2,
    float* __restrict__ hout, float* __restrict__ sum, float* __restrict__ sumsq)
{
    __shared__ float sW1[HH * HH];
    __shared__ float sW2[HH * HH];
    __shared__ float sh[ROWS][HH];
    __shared__ float sh1[ROWS][HH];

    int tid = threadIdx.y * HH + threadIdx.x;
    // cooperative load of both weight matrices (4096 floats each) as float4
    for (int i = tid; i < HH * HH / 4; i += 512) {
        reinterpret_cast<float4*>(sW1)[i] = reinterpret_cast<const float4*>(W1)[i];
        reinterpret_cast<float4*>(sW2)[i] = reinterpret_cast<const float4*>(W2)[i];
    }

    const int col = threadIdx.x;
    const int r   = threadIdx.y;
    const int row = blockIdx.x * ROWS + r;

    float hv = x[row * HH + col] + agg[row * HH + col];
    sh[r][col] = hv;
    __syncthreads();

    float acc = b1[col];
    #pragma unroll
    for (int k = 0; k < HH; k++)
        acc = fmaf(sh[r][k], sW1[k * HH + col], acc);
    sh1[r][col] = fmaxf(acc, 0.0f);
    __syncthreads();

    float acc2 = b2[col];
    #pragma unroll
    for (int k = 0; k < HH; k++)
        acc2 = fmaf(sh1[r][k], sW2[k * HH + col], acc2);
    hout[row * HH + col] = acc2;

    sh[r][col] = acc2;
    __syncthreads();
    if (r == 0) {
        float s = 0.0f, sq = 0.0f;
        #pragma unroll
        for (int rr = 0; rr < ROWS; rr++) {
            float v = sh[rr][col];
            s += v; sq += v * v;
        }
        atomicAdd(&sum[col], s);
        atomicAdd(&sumsq[col], sq);
    }
}

// -------- BN apply + ReLU (+ optional fused mean-pool accumulation) --------
template <bool DO_POOL>
__global__ __launch_bounds__(256) void bn_apply_kernel(
    const float* __restrict__ h, const float* __restrict__ sum,
    const float* __restrict__ sumsq, const float* __restrict__ g,
    const float* __restrict__ be, float* __restrict__ y,
    const int* __restrict__ batch, float* __restrict__ gsum,
    float* __restrict__ gcnt)
{
    int idx = blockIdx.x * blockDim.x + threadIdx.x;
    if (idx >= NN * HH) return;
    int col = idx & (HH - 1);
    int row = idx >> 6;
    const float invN = 1.0f / (float)NN;
    float mu  = sum[col] * invN;
    float var = sumsq[col] * invN - mu * mu;
    float rs  = rsqrtf(var + BN_EPS);
    float v = fmaxf((h[idx] - mu) * rs * g[col] + be[col], 0.0f);
    y[idx] = v;
    if (DO_POOL) {
        int bg = batch[row];
        atomicAdd(&gsum[bg * HH + col], v);
        if (col == 0) atomicAdd(&gcnt[bg], 1.0f);
    }
}

__global__ void pool_final_kernel(const float* __restrict__ gsum,
                                  const float* __restrict__ gcnt,
                                  float* __restrict__ out)
{
    int i = blockIdx.x * blockDim.x + threadIdx.x;
    if (i >= GG * HH) return;
    int g = i >> 6;
    out[i] = gsum[i] / fmaxf(gcnt[g], 1.0f);
}

extern "C" void kernel_launch(void* const* d_in, const int* in_sizes, int n_in,
                              void* d_out, int out_size)
{
    const float* x     = (const float*)d_in[0];
    const int*   ei    = (const int*)d_in[1];
    const int*   batch = (const int*)d_in[2];
    const float* W1_0 = (const float*)d_in[3];
    const float* b1_0 = (const float*)d_in[4];
    const float* W2_0 = (const float*)d_in[5];
    const float* b2_0 = (const float*)d_in[6];
    const float* g_0  = (const float*)d_in[7];
    const float* be_0 = (const float*)d_in[8];
    const float* W1_1 = (const float*)d_in[9];
    const float* b1_1 = (const float*)d_in[10];
    const float* W2_1 = (const float*)d_in[11];
    const float* b2_1 = (const float*)d_in[12];
    const float* g_1  = (const float*)d_in[13];
    const float* be_1 = (const float*)d_in[14];

    float* out_x = (float*)d_out;                 // [N, H]
    float* out_g = (float*)d_out + NN * HH;       // [G, H]

    void *p_agg, *p_sum, *p_sumsq, *p_h, *p_x1, *p_gsum, *p_gcnt;
    cudaGetSymbolAddress(&p_agg, d_agg);
    cudaGetSymbolAddress(&p_sum, d_sum);
    cudaGetSymbolAddress(&p_sumsq, d_sumsq);
    cudaGetSymbolAddress(&p_h, d_h);
    cudaGetSymbolAddress(&p_x1, d_x1);
    cudaGetSymbolAddress(&p_gsum, d_gsum);
    cudaGetSymbolAddress(&p_gcnt, d_gcnt);

    const long long scatter_threads = (long long)EE * 16;
    const int scatter_blocks = (int)((scatter_threads + 255) / 256);
    const dim3 mlp_block(HH, ROWS);
    const int mlp_blocks = NN / ROWS;   // 6250 exactly
    const int ew_blocks = (NN * HH + 255) / 256;

    // ---------------- layer 0 ----------------
    cudaMemsetAsync(p_agg, 0, sizeof(float) * NN * HH, 0);
    cudaMemsetAsync(p_sum, 0, sizeof(float) * HH, 0);
    cudaMemsetAsync(p_sumsq, 0, sizeof(float) * HH, 0);

    scatter_kernel<<<scatter_blocks, 256>>>(x, ei, (float*)p_agg);
    mlp_kernel<<<mlp_blocks, mlp_block>>>(x, (const float*)p_agg,
        W1_0, b1_0, W2_0, b2_0, (float*)p_h, (float*)p_sum, (float*)p_sumsq);
    bn_apply_kernel<false><<<ew_blocks, 256>>>((const float*)p_h,
        (const float*)p_sum, (const float*)p_sumsq, g_0, be_0,
        (float*)p_x1, batch, nullptr, nullptr);

    // ---------------- layer 1 ----------------
    cudaMemsetAsync(p_agg, 0, sizeof(float) * NN * HH, 0);
    cudaMemsetAsync(p_sum, 0, sizeof(float) * HH, 0);
    cudaMemsetAsync(p_sumsq, 0, sizeof(float) * HH, 0);
    cudaMemsetAsync(p_gsum, 0, sizeof(float) * GG * HH, 0);
    cudaMemsetAsync(p_gcnt, 0, sizeof(float) * GG, 0);

    scatter_kernel<<<scatter_blocks, 256>>>((const float*)p_x1, ei, (float*)p_agg);
    mlp_kernel<<<mlp_blocks, mlp_block>>>((const float*)p_x1, (const float*)p_agg,
        W1_1, b1_1, W2_1, b2_1, (float*)p_h, (float*)p_sum, (float*)p_sumsq);
    bn_apply_kernel<true><<<ew_blocks, 256>>>((const float*)p_h,
        (const float*)p_sum, (const float*)p_sumsq, g_1, be_1,
        out_x, batch, (float*)p_gsum, (float*)p_gcnt);

    pool_final_kernel<<<(GG * HH + 255) / 256, 256>>>(
        (const float*)p_gsum, (const float*)p_gcnt, out_g);
}

// round 3
// speedup vs baseline: 1.1500x; 1.1500x over previous
#include <cuda_runtime.h>
#include <cuda_bf16.h>

#define NN 50000
#define EE 800000
#define HH 64
#define GG 16
#define BN_EPS 1e-5f
#define RT 16           // rows (nodes) per block in fused kernel
#define SCAN_T 1024

// -------- scratch --------
__device__ float d_h[NN * HH];      // pre-BN MLP output
__device__ float d_x1[NN * HH];     // layer-1 output
__device__ float d_sum[HH];
__device__ float d_sumsq[HH];
__device__ float d_gsum[GG * HH];
__device__ float d_gcnt[GG];
__device__ int   d_off[NN + 1];
__device__ int   d_cur[NN];         // counts, then running cursor
__device__ int   d_csr[EE];         // src ids grouped by dst

// ================= CSR build =================
__global__ __launch_bounds__(256) void hist_kernel(const int* __restrict__ ei,
                                                   int* __restrict__ cnt)
{
    int e = blockIdx.x * blockDim.x + threadIdx.x;
    if (e < EE) atomicAdd(&cnt[ei[EE + e]], 1);
}

__global__ __launch_bounds__(SCAN_T) void scan_kernel(int* __restrict__ cur,
                                                      int* __restrict__ off)
{
    __shared__ int part[SCAN_T];
    const int t = threadIdx.x;
    const int chunk = (NN + SCAN_T - 1) / SCAN_T;   // 49
    const int lo = t * chunk;
    const int hi = min(lo + chunk, NN);
    int s = 0;
    for (int i = lo; i < hi; i++) s += cur[i];
    part[t] = s;
    __syncthreads();
    // inclusive Hillis-Steele scan
    for (int d = 1; d < SCAN_T; d <<= 1) {
        int v = (t >= d) ? part[t - d] : 0;
        __syncthreads();
        part[t] += v;
        __syncthreads();
    }
    int run = (t == 0) ? 0 : part[t - 1];           // exclusive base
    for (int i = lo; i < hi; i++) {
        int c = cur[i];
        off[i] = run;
        cur[i] = run;   // cursor starts at segment base
        run += c;
    }
    if (t == SCAN_T - 1) off[NN] = EE;
}

__global__ __launch_bounds__(256) void fill_kernel(const int* __restrict__ ei,
                                                   int* __restrict__ cur,
                                                   int* __restrict__ csr)
{
    int e = blockIdx.x * blockDim.x + threadIdx.x;
    if (e >= EE) return;
    int s = ei[e];
    int d = ei[EE + e];
    int pos = atomicAdd(&cur[d], 1);
    csr[pos] = s;
}

// ====== fused: CSR gather + (x+agg) -> Linear/ReLU/Linear -> hout + BN stats ======
__global__ __launch_bounds__(256) void fused_mlp_kernel(
    const float* __restrict__ x, const int* __restrict__ off,
    const int* __restrict__ csr,
    const float* __restrict__ W1, const float* __restrict__ b1,
    const float* __restrict__ W2, const float* __restrict__ b2,
    float* __restrict__ hout, float* __restrict__ sum, float* __restrict__ sumsq)
{
    __shared__ alignas(16) float sW1[HH * HH];
    __shared__ alignas(16) float sW2[HH * HH];
    __shared__ alignas(16) float sh[RT][HH];
    __shared__ alignas(16) float sh1[RT][HH];
    __shared__ float ps[4][HH];
    __shared__ float psq[4][HH];

    const int tid  = threadIdx.x;            // 0..255
    const int base = blockIdx.x * RT;

    // cooperative weight load (both matrices, float4)
    for (int i = tid; i < HH * HH / 4; i += 256) {
        reinterpret_cast<float4*>(sW1)[i] = reinterpret_cast<const float4*>(W1)[i];
        reinterpret_cast<float4*>(sW2)[i] = reinterpret_cast<const float4*>(W2)[i];
    }

    // ---- gather phase: warp w handles nodes base+2w, base+2w+1 ----
    {
        const int w = tid >> 5;
        const int l = tid & 31;
        #pragma unroll
        for (int j = 0; j < 2; j++) {
            const int r = 2 * w + j;
            const int node = base + r;
            const float* xr = x + (long long)node * HH + 2 * l;
            float2 acc = *reinterpret_cast<const float2*>(xr);
            const int jb = off[node], je = off[node + 1];
            for (int p = jb; p < je; p++) {
                int nbr = csr[p];
                float2 v = *reinterpret_cast<const float2*>(x + (long long)nbr * HH + 2 * l);
                acc.x += v.x; acc.y += v.y;
            }
            *reinterpret_cast<float2*>(&sh[r][2 * l]) = acc;
        }
    }
    __syncthreads();

    // ---- GEMM1: sh1 = relu(sh @ W1 + b1), 4 rows per thread ----
    const int col = tid & 63;
    const int rg  = tid >> 6;            // 0..3
    const int r0  = rg * 4;
    {
        float a0 = b1[col], a1 = a0, a2 = a0, a3 = a0;
        #pragma unroll
        for (int kv = 0; kv < HH / 4; kv++) {
            float4 h0 = *reinterpret_cast<const float4*>(&sh[r0 + 0][kv * 4]);
            float4 h1 = *reinterpret_cast<const float4*>(&sh[r0 + 1][kv * 4]);
            float4 h2 = *reinterpret_cast<const float4*>(&sh[r0 + 2][kv * 4]);
            float4 h3 = *reinterpret_cast<const float4*>(&sh[r0 + 3][kv * 4]);
            float w0 = sW1[(kv * 4 + 0) * HH + col];
            float w1 = sW1[(kv * 4 + 1) * HH + col];
            float w2 = sW1[(kv * 4 + 2) * HH + col];
            float w3 = sW1[(kv * 4 + 3) * HH + col];
            a0 = fmaf(h0.x, w0, fmaf(h0.y, w1, fmaf(h0.z, w2, fmaf(h0.w, w3, a0))));
            a1 = fmaf(h1.x, w0, fmaf(h1.y, w1, fmaf(h1.z, w2, fmaf(h1.w, w3, a1))));
            a2 = fmaf(h2.x, w0, fmaf(h2.y, w1, fmaf(h2.z, w2, fmaf(h2.w, w3, a2))));
            a3 = fmaf(h3.x, w0, fmaf(h3.y, w1, fmaf(h3.z, w2, fmaf(h3.w, w3, a3))));
        }
        sh1[r0 + 0][col] = fmaxf(a0, 0.0f);
        sh1[r0 + 1][col] = fmaxf(a1, 0.0f);
        sh1[r0 + 2][col] = fmaxf(a2, 0.0f);
        sh1[r0 + 3][col] = fmaxf(a3, 0.0f);
    }
    __syncthreads();

    // ---- GEMM2: h2 = sh1 @ W2 + b2 ; write hout ; BN partials ----
    {
        float a0 = b2[col], a1 = a0, a2 = a0, a3 = a0;
        #pragma unroll
        for (int kv = 0; kv < HH / 4; kv++) {
            float4 h0 = *reinterpret_cast<const float4*>(&sh1[r0 + 0][kv * 4]);
            float4 h1 = *reinterpret_cast<const float4*>(&sh1[r0 + 1][kv * 4]);
            float4 h2 = *reinterpret_cast<const float4*>(&sh1[r0 + 2][kv * 4]);
            float4 h3 = *reinterpret_cast<const float4*>(&sh1[r0 + 3][kv * 4]);
            float w0 = sW2[(kv * 4 + 0) * HH + col];
            float w1 = sW2[(kv * 4 + 1) * HH + col];
            float w2 = sW2[(kv * 4 + 2) * HH + col];
            float w3 = sW2[(kv * 4 + 3) * HH + col];
            a0 = fmaf(h0.x, w0, fmaf(h0.y, w1, fmaf(h0.z, w2, fmaf(h0.w, w3, a0))));
            a1 = fmaf(h1.x, w0, fmaf(h1.y, w1, fmaf(h1.z, w2, fmaf(h1.w, w3, a1))));
            a2 = fmaf(h2.x, w0, fmaf(h2.y, w1, fmaf(h2.z, w2, fmaf(h2.w, w3, a2))));
            a3 = fmaf(h3.x, w0, fmaf(h3.y, w1, fmaf(h3.z, w2, fmaf(h3.w, w3, a3))));
        }
        hout[(long long)(base + r0 + 0) * HH + col] = a0;
        hout[(long long)(base + r0 + 1) * HH + col] = a1;
        hout[(long long)(base + r0 + 2) * HH + col] = a2;
        hout[(long long)(base + r0 + 3) * HH + col] = a3;
        ps[rg][col]  = a0 + a1 + a2 + a3;
        psq[rg][col] = a0 * a0 + a1 * a1 + a2 * a2 + a3 * a3;
    }
    __syncthreads();
    if (tid < HH) {
        float s  = ps[0][tid] + ps[1][tid] + ps[2][tid] + ps[3][tid];
        float sq = psq[0][tid] + psq[1][tid] + psq[2][tid] + psq[3][tid];
        atomicAdd(&sum[tid], s);
        atomicAdd(&sumsq[tid], sq);
    }
}

// -------- BN apply + ReLU (+ optional fused mean-pool accumulation) --------
template <bool DO_POOL>
__global__ __launch_bounds__(256) void bn_apply_kernel(
    const float* __restrict__ h, const float* __restrict__ sum,
    const float* __restrict__ sumsq, const float* __restrict__ g,
    const float* __restrict__ be, float* __restrict__ y,
    const int* __restrict__ batch, float* __restrict__ gsum,
    float* __restrict__ gcnt)
{
    int idx = blockIdx.x * blockDim.x + threadIdx.x;
    if (idx >= NN * HH) return;
    int col = idx & (HH - 1);
    int row = idx >> 6;
    const float invN = 1.0f / (float)NN;
    float mu  = sum[col] * invN;
    float var = sumsq[col] * invN - mu * mu;
    float rs  = rsqrtf(var + BN_EPS);
    float v = fmaxf((h[idx] - mu) * rs * g[col] + be[col], 0.0f);
    y[idx] = v;
    if (DO_POOL) {
        int bg = batch[row];
        atomicAdd(&gsum[bg * HH + col], v);
        if (col == 0) atomicAdd(&gcnt[bg], 1.0f);
    }
}

__global__ void pool_final_kernel(const float* __restrict__ gsum,
                                  const float* __restrict__ gcnt,
                                  float* __restrict__ out)
{
    int i = blockIdx.x * blockDim.x + threadIdx.x;
    if (i >= GG * HH) return;
    int g = i >> 6;
    out[i] = gsum[i] / fmaxf(gcnt[g], 1.0f);
}

extern "C" void kernel_launch(void* const* d_in, const int* in_sizes, int n_in,
                              void* d_out, int out_size)
{
    const float* x     = (const float*)d_in[0];
    const int*   ei    = (const int*)d_in[1];
    const int*   batch = (const int*)d_in[2];
    const float* W1_0 = (const float*)d_in[3];
    const float* b1_0 = (const float*)d_in[4];
    const float* W2_0 = (const float*)d_in[5];
    const float* b2_0 = (const float*)d_in[6];
    const float* g_0  = (const float*)d_in[7];
    const float* be_0 = (const float*)d_in[8];
    const float* W1_1 = (const float*)d_in[9];
    const float* b1_1 = (const float*)d_in[10];
    const float* W2_1 = (const float*)d_in[11];
    const float* b2_1 = (const float*)d_in[12];
    const float* g_1  = (const float*)d_in[13];
    const float* be_1 = (const float*)d_in[14];

    float* out_x = (float*)d_out;                 // [N, H]
    float* out_g = (float*)d_out + NN * HH;       // [G, H]

    void *p_sum, *p_sumsq, *p_h, *p_x1, *p_gsum, *p_gcnt, *p_off, *p_cur, *p_csr;
    cudaGetSymbolAddress(&p_sum, d_sum);
    cudaGetSymbolAddress(&p_sumsq, d_sumsq);
    cudaGetSymbolAddress(&p_h, d_h);
    cudaGetSymbolAddress(&p_x1, d_x1);
    cudaGetSymbolAddress(&p_gsum, d_gsum);
    cudaGetSymbolAddress(&p_gcnt, d_gcnt);
    cudaGetSymbolAddress(&p_off, d_off);
    cudaGetSymbolAddress(&p_cur, d_cur);
    cudaGetSymbolAddress(&p_csr, d_csr);

    const int fused_blocks = NN / RT;                 // 3125
    const int ew_blocks = (NN * HH + 255) / 256;
    const int e_blocks = (EE + 255) / 256;

    // ---------------- CSR build (once, reused for both layers) ----------------
    cudaMemsetAsync(p_cur, 0, sizeof(int) * NN, 0);
    hist_kernel<<<e_blocks, 256>>>(ei, (int*)p_cur);
    scan_kernel<<<1, SCAN_T>>>((int*)p_cur, (int*)p_off);
    fill_kernel<<<e_blocks, 256>>>(ei, (int*)p_cur, (int*)p_csr);

    // ---------------- layer 0 ----------------
    cudaMemsetAsync(p_sum, 0, sizeof(float) * HH, 0);
    cudaMemsetAsync(p_sumsq, 0, sizeof(float) * HH, 0);
    fused_mlp_kernel<<<fused_blocks, 256>>>(x, (const int*)p_off, (const int*)p_csr,
        W1_0, b1_0, W2_0, b2_0, (float*)p_h, (float*)p_sum, (float*)p_sumsq);
    bn_apply_kernel<false><<<ew_blocks, 256>>>((const float*)p_h,
        (const float*)p_sum, (const float*)p_sumsq, g_0, be_0,
        (float*)p_x1, batch, nullptr, nullptr);

    // ---------------- layer 1 ----------------
    cudaMemsetAsync(p_sum, 0, sizeof(float) * HH, 0);
    cudaMemsetAsync(p_sumsq, 0, sizeof(float) * HH, 0);
    cudaMemsetAsync(p_gsum, 0, sizeof(float) * GG * HH, 0);
    cudaMemsetAsync(p_gcnt, 0, sizeof(float) * GG, 0);
    fused_mlp_kernel<<<fused_blocks, 256>>>((const float*)p_x1, (const int*)p_off,
        (const int*)p_csr,
        W1_1, b1_1, W2_1, b2_1, (float*)p_h, (float*)p_sum, (float*)p_sumsq);
    bn_apply_kernel<true><<<ew_blocks, 256>>>((const float*)p_h,
        (const float*)p_sum, (const float*)p_sumsq, g_1, be_1,
        out_x, batch, (float*)p_gsum, (float*)p_gcnt);

    pool_final_kernel<<<(GG * HH + 255) / 256, 256>>>(
        (const float*)p_gsum, (const float*)p_gcnt, out_g);
}